// round 16
// baseline (speedup 1.0000x reference)
#include <cuda_runtime.h>
#include <cuda_fp16.h>
#include <cstdint>

// ---------------- problem dims ----------------
#define BATCH 16
#define IC1   128
#define OCN   256
#define ZDIM  64
#define HIN   64
#define WIN   64
#define HO    32
#define WO    32
#define NPIX  1024
#define NGRP  8
#define EPSV  1e-5f
#define PW1   66     // padded x: 66x66
#define PW2   34     // padded act1: 34x34

// ---------------- scratch (__device__ globals zero-init; halos stay 0) ----------------
__device__ __half g_xh [(size_t)BATCH*PW1*PW1*IC1];
__device__ __half g_ah [(size_t)BATCH*PW2*PW2*OCN];
__device__ __half g_w1 [(size_t)BATCH*9*OCN*IC1];
__device__ __half g_w2 [(size_t)BATCH*9*OCN*OCN];
__device__ __half g_ws [(size_t)BATCH*OCN*IC1];
__device__ __half g_c1 [(size_t)BATCH*NPIX*OCN];    // NHWC fp16 conv outputs
__device__ __half g_c2 [(size_t)BATCH*NPIX*OCN];
__device__ __half g_sc [(size_t)BATCH*NPIX*OCN];
__device__ float g_st1[BATCH*NGRP*2];
__device__ float g_st2[BATCH*NGRP*2];
// per-block GN partials: [b*8+g][8 px-tiles]
__device__ float g_p1s[BATCH*NGRP*8];
__device__ float g_p1q[BATCH*NGRP*8];
__device__ float g_p2s[BATCH*NGRP*8];
__device__ float g_p2q[BATCH*NGRP*8];

// ---------------- helpers ----------------
__device__ __forceinline__ uint32_t smem_u32(const void* p) {
    uint32_t a;
    asm("{ .reg .u64 t; cvta.to.shared.u64 t, %1; cvt.u32.u64 %0, t; }" : "=r"(a) : "l"(p));
    return a;
}
#define SWZ(x) ((uint32_t)(x) ^ ((((uint32_t)(x)) >> 3) & 0x70u))

#define CP16(dst, src) \
    asm volatile("cp.async.cg.shared.global [%0], [%1], 16;" :: "r"(dst), "l"(src))
#define CPCOMMIT() asm volatile("cp.async.commit_group;" ::: "memory")
#define CPWAIT0()  asm volatile("cp.async.wait_group 0;" ::: "memory")

#define LDSM4(r, addr) \
    asm volatile("ldmatrix.sync.aligned.m8n8.x4.shared.b16 {%0,%1,%2,%3}, [%4];" \
                 : "=r"((r)[0]), "=r"((r)[1]), "=r"((r)[2]), "=r"((r)[3]) : "r"(addr))

#define MMA16816(c, a, b0, b1) \
    asm volatile("mma.sync.aligned.m16n8k16.row.col.f32.f16.f16.f32 " \
                 "{%0,%1,%2,%3}, {%4,%5,%6,%7}, {%8,%9}, {%0,%1,%2,%3};" \
                 : "+f"((c)[0]), "+f"((c)[1]), "+f"((c)[2]), "+f"((c)[3]) \
                 : "r"((a)[0]), "r"((a)[1]), "r"((a)[2]), "r"((a)[3]), "r"(b0), "r"(b1))

__device__ __forceinline__ uint32_t pk_h2(float a, float b) {
    __half2 t = __floats2half2_rn(a, b);
    return *(uint32_t*)&t;
}
__device__ __forceinline__ float2 uph2(uint32_t v) {
    __half2 h = *(__half2*)&v;
    return __half22float2(h);
}

// ---------------- prep: x NCHW fp32 -> padded NHWC fp16 ----------------
__global__ __launch_bounds__(256) void prep_x_kernel(
    const float* __restrict__ x, __half* __restrict__ xh)
{
    __shared__ float s[32][33];
    const int wt = blockIdx.x & 1, ct = blockIdx.x >> 1;
    const int h = blockIdx.y, b = blockIdx.z;
    const int w0 = wt * 32, c0 = ct * 32;
    const int tx = threadIdx.x;
#pragma unroll
    for (int k = 0; k < 4; k++) {
        int idx = tx + k * 256;
        int ci = idx >> 5, wi = idx & 31;
        s[wi][ci] = x[(((size_t)b * IC1 + c0 + ci) * HIN + h) * WIN + w0 + wi];
    }
    __syncthreads();
    const int wi = tx >> 3, cg = tx & 7;
    size_t o = (((size_t)b * PW1 + h + 1) * PW1 + (w0 + wi + 1)) * IC1 + c0 + cg * 4;
    *(uint2*)(xh + o) = make_uint2(pk_h2(s[wi][cg*4+0], s[wi][cg*4+1]),
                                   pk_h2(s[wi][cg*4+2], s[wi][cg*4+3]));
}

// ---------------- weight modulation via tensor cores ------------------------------
// delta[row, b] = hw[row, 0:64] . z[b, 0:64]; out = fp16(base + hb + delta).
// Block: 128 rows x 16 batches, K=64. hw staged fp16 (swizzled); z as hi/lo-split
// fp16 B fragments (2 MMA passes -> z rounding error cancels). fp32 accum.
// Row gi = (oc*IC + ic)*NTAP + tap; block handles rows [ (blk0+bid)*128, +128 ).
template<int NTAP, int IC>
__global__ __launch_bounds__(256) void modw_mma_kernel(
    const float* __restrict__ base, const float* __restrict__ hw,
    const float* __restrict__ hb,   const float* __restrict__ z,
    __half* __restrict__ wout, int blk0)
{
    __shared__ __half hwS[128 * 64];
    __shared__ float cb[128];
    const int tx = threadIdx.x, lane = tx & 31, wid = tx >> 5;
    const int row0 = (blk0 + (int)blockIdx.x) * 128;

    // stage hw rows (fp32 -> fp16, SW128 swizzled; 128B per row)
#pragma unroll
    for (int p = 0; p < 8; p++) {
        int idx = tx + p * 256;                 // float4 index
        int row = idx >> 4, k0 = (idx & 15) * 4;
        float4 v = *(const float4*)(hw + (size_t)(row0 + row) * ZDIM + k0);
        uint32_t so = SWZ(row * 128 + k0 * 2);
        *(uint2*)((char*)hwS + so) = make_uint2(pk_h2(v.x, v.y), pk_h2(v.z, v.w));
    }
    if (tx < 128) cb[tx] = base[row0 + tx] + hb[row0 + tx];

    // z B-fragments (hi/lo split), built once per thread
    uint32_t zhi[4][2][2], zlo[4][2][2];
#pragma unroll
    for (int ks = 0; ks < 4; ks++)
#pragma unroll
        for (int nt = 0; nt < 2; nt++)
#pragma unroll
            for (int rg = 0; rg < 2; rg++) {
                int n = (lane >> 2) + nt * 8;
                int k = ks * 16 + (lane & 3) * 2 + rg * 8;
                float a = z[n * ZDIM + k], bq = z[n * ZDIM + k + 1];
                __half ah = __float2half_rn(a), bh = __float2half_rn(bq);
                __half2 thi = __halves2half2(ah, bh);
                __half2 tlo = __halves2half2(__float2half_rn(a - __half2float(ah)),
                                             __float2half_rn(bq - __half2float(bh)));
                zhi[ks][nt][rg] = *(uint32_t*)&thi;
                zlo[ks][nt][rg] = *(uint32_t*)&tlo;
            }
    __syncthreads();

    float c[2][4] = {};
    const uint32_t sbase = smem_u32(hwS);
    const int arow = wid * 16 + (lane & 7) + ((lane >> 3) & 1) * 8;
    const int acol = ((lane >> 4) & 1) * 16;
#pragma unroll
    for (int ks = 0; ks < 4; ks++) {
        uint32_t a[4];
        LDSM4(a, sbase + SWZ(arow * 128 + acol + ks * 32));
#pragma unroll
        for (int nt = 0; nt < 2; nt++) {
            MMA16816(c[nt], a, zhi[ks][nt][0], zhi[ks][nt][1]);
            MMA16816(c[nt], a, zlo[ks][nt][0], zlo[ks][nt][1]);
        }
    }

    // epilogue: scatter to [b][tap][oc][ic]
#pragma unroll
    for (int half = 0; half < 2; half++) {
        int r  = wid * 16 + (lane >> 2) + half * 8;
        int gr = row0 + r;
        int tap = gr % NTAP;
        int rem = gr / NTAP;
        int ic = rem % IC, oc = rem / IC;
        float add = cb[r];
        size_t obase = ((size_t)tap * OCN + oc) * IC + ic;
#pragma unroll
        for (int nt = 0; nt < 2; nt++) {
            int b0 = (lane & 3) * 2 + nt * 8;
            wout[(size_t)(b0 + 0) * ((size_t)NTAP * OCN * IC) + obase] =
                __float2half_rn(c[nt][half * 2 + 0] + add);
            wout[(size_t)(b0 + 1) * ((size_t)NTAP * OCN * IC) + obase] =
                __float2half_rn(c[nt][half * 2 + 1] + add);
        }
    }
}

// ---------------- weight modulation (1x1 shortcut): one thread per row (exact fp32) --
__global__ __launch_bounds__(256) void modw1_kernel(
    const float* __restrict__ base, const float* __restrict__ hw,
    const float* __restrict__ hb,   const float* __restrict__ z,
    __half* __restrict__ wout)
{
    __shared__ float zs[BATCH * ZDIM];
    for (int i = threadIdx.x; i < BATCH * ZDIM; i += 256) zs[i] = z[i];
    __syncthreads();

    const int i = blockIdx.x * 256 + threadIdx.x;
    float4 hwv[16];
    const float4* hwp = (const float4*)(hw + (size_t)i * ZDIM);
#pragma unroll
    for (int j = 0; j < 16; j++) hwv[j] = hwp[j];
    const float c = base[i] + hb[i];
#pragma unroll
    for (int b = 0; b < BATCH; b++) {
        const float* zb = zs + b * ZDIM;
        float acc = 0.f;
#pragma unroll
        for (int j = 0; j < 16; j++) {
            acc += hwv[j].x * zb[4*j+0];
            acc += hwv[j].y * zb[4*j+1];
            acc += hwv[j].z * zb[4*j+2];
            acc += hwv[j].w * zb[4*j+3];
        }
        wout[(size_t)b * (OCN * IC1) + i] = __float2half_rn(c + acc);
    }
}

// ---------------- conv: fp16 1-pass, A shared across taps, fused GN partials --------
template<int IC, int S, int PW, int FSC>
__global__ __launch_bounds__(256) void conv_mma_kernel(
    const __half* __restrict__ ain,
    const __half* __restrict__ win,
    const __half* __restrict__ wsin,
    __half* __restrict__ outp, __half* __restrict__ outsc,
    float* __restrict__ ps, float* __restrict__ pq)
{
    constexpr int IW_T = 31 * S + 3;
    constexpr int IH_T = 3 * S + 3;
    constexpr int APX  = IH_T * IW_T;
    constexpr int ABYT = APX * 128;
    constexpr int NT   = 9 + FSC;

    extern __shared__ char smem_raw[];
    uint32_t sb = smem_u32(smem_raw);
    sb = (sb + 1023) & ~1023u;
    const uint32_t S_A = sb, S_B = sb + ABYT;
    __shared__ float redS[4], redQ[4];

    const int tx = threadIdx.x, lane = tx & 31, wid = tx >> 5;
    const int warpM = wid & 3, warpN = wid >> 2;
    const int mbase = warpM * 32, nbase = warpN * 64;

    const int b = blockIdx.z, oc0g = blockIdx.y * 128;
    const int oh0 = blockIdx.x * 4, p0 = blockIdx.x * 128;
    const size_t abase = (size_t)b * PW * PW * IC;

    const int colsel = ((lane >> 4) & 1) * 16;
    int ohl[2], owl[2];
#pragma unroll
    for (int mt = 0; mt < 2; mt++) {
        int opx = mbase + mt * 16 + (lane & 15);
        ohl[mt] = opx >> 5; owl[mt] = opx & 31;
    }
    int rB[4];
#pragma unroll
    for (int p = 0; p < 4; p++)
        rB[p] = (nbase + p * 16 + (lane & 7) + ((lane >> 4) & 1) * 8) * 128
              + ((lane >> 3) & 1) * 16;

    float acc[2][8][4] = {};
    float accs[FSC ? 2 : 1][FSC ? 8 : 1][4] = {};

    auto stageB = [&](int icc, int tap, int buf) {
        uint32_t BH = S_B + (uint32_t)buf * 16384u;
        const __half* sh; size_t wb;
        if (FSC && tap == 9) {
            sh = wsin;
            wb = ((size_t)b * OCN + oc0g) * IC;
        } else {
            sh = win;
            wb = (((size_t)b * 9 + tap) * OCN + oc0g) * IC;
        }
#pragma unroll
        for (int pass = 0; pass < 4; pass++) {
            int i = tx + pass * 256;
            int row = i >> 3, chk = i & 7;
            size_t src = wb + (size_t)row * IC + icc * 64 + chk * 8;
            CP16(BH + SWZ(row * 128 + chk * 16), (const char*)(sh + src));
        }
    };

#define MMA_PHASE(ACC)                                                          \
    {                                                                           \
        int arow0 = (ohl[0] * S + dh) * IW_T + owl[0] * S + dw;                 \
        int arow1 = (ohl[1] * S + dh) * IW_T + owl[1] * S + dw;                 \
        _Pragma("unroll")                                                       \
        for (int ks = 0; ks < 4; ks++) {                                        \
            uint32_t ah[2][4], bfr[4][4];                                       \
            LDSM4(ah[0], S_A + SWZ(arow0 * 128 + colsel + ks * 32));            \
            LDSM4(ah[1], S_A + SWZ(arow1 * 128 + colsel + ks * 32));            \
            _Pragma("unroll")                                                   \
            for (int p = 0; p < 4; p++) LDSM4(bfr[p], SB + SWZ(rB[p] + ks * 32)); \
            _Pragma("unroll")                                                   \
            for (int mt = 0; mt < 2; mt++)                                      \
                _Pragma("unroll")                                               \
                for (int nt = 0; nt < 8; nt++)                                  \
                    MMA16816(ACC[mt][nt], ah[mt], bfr[nt >> 1][(nt & 1) * 2],   \
                             bfr[nt >> 1][(nt & 1) * 2 + 1]);                   \
        }                                                                       \
    }

#pragma unroll 1
    for (int icc = 0; icc < IC / 64; icc++) {
        __syncthreads();
        for (int i = tx; i < APX * 8; i += 256) {
            int row = i >> 3, chk = i & 7;
            int ihl = row / IW_T, iw = row - ihl * IW_T;
            size_t src = abase + ((size_t)(oh0 * S + ihl) * PW + iw) * IC
                       + icc * 64 + chk * 8;
            CP16(S_A + SWZ(row * 128 + chk * 16), (const char*)(ain + src));
        }
        stageB(icc, 0, 0);
        CPCOMMIT();

#pragma unroll 1
        for (int tap = 0; tap < NT; tap++) {
            CPWAIT0();
            __syncthreads();
            if (tap + 1 < NT) { stageB(icc, tap + 1, (tap + 1) & 1); CPCOMMIT(); }

            const int dh = (FSC && tap == 9) ? 1 : tap / 3;
            const int dw = (FSC && tap == 9) ? 1 : tap % 3;
            const uint32_t SB = S_B + (uint32_t)(tap & 1) * 16384u;
            if (FSC && tap == 9) { MMA_PHASE(accs) }
            else                 { MMA_PHASE(acc)  }
        }
    }

    // ---- epilogue: NHWC fp16 + per-group fp32 partial stats ----
    if (tx < 4) { redS[tx] = 0.f; redQ[tx] = 0.f; }
    __syncthreads();

    __half* ob = outp + (size_t)b * NPIX * OCN + oc0g;
    float s0 = 0.f, q0 = 0.f, s1 = 0.f, q1 = 0.f;
#pragma unroll
    for (int mt = 0; mt < 2; mt++) {
        int px0 = p0 + mbase + mt * 16 + (lane >> 2);
#pragma unroll
        for (int nt = 0; nt < 8; nt++) {
            int oc = nbase + nt * 8 + (lane & 3) * 2;
            *(uint32_t*)(ob + (size_t)px0 * OCN + oc) = pk_h2(acc[mt][nt][0], acc[mt][nt][1]);
            *(uint32_t*)(ob + (size_t)(px0 + 8) * OCN + oc) = pk_h2(acc[mt][nt][2], acc[mt][nt][3]);
            float ls = acc[mt][nt][0] + acc[mt][nt][1] + acc[mt][nt][2] + acc[mt][nt][3];
            float lq = acc[mt][nt][0]*acc[mt][nt][0] + acc[mt][nt][1]*acc[mt][nt][1]
                     + acc[mt][nt][2]*acc[mt][nt][2] + acc[mt][nt][3]*acc[mt][nt][3];
            if (nt < 4) { s0 += ls; q0 += lq; } else { s1 += ls; q1 += lq; }
        }
    }
#pragma unroll
    for (int off = 16; off > 0; off >>= 1) {
        s0 += __shfl_down_sync(0xffffffffu, s0, off);
        q0 += __shfl_down_sync(0xffffffffu, q0, off);
        s1 += __shfl_down_sync(0xffffffffu, s1, off);
        q1 += __shfl_down_sync(0xffffffffu, q1, off);
    }
    if (lane == 0) {
        atomicAdd(&redS[warpN * 2 + 0], s0); atomicAdd(&redQ[warpN * 2 + 0], q0);
        atomicAdd(&redS[warpN * 2 + 1], s1); atomicAdd(&redQ[warpN * 2 + 1], q1);
    }

    if (FSC) {
        __half* os = outsc + (size_t)b * NPIX * OCN + oc0g;
#pragma unroll
        for (int mt = 0; mt < 2; mt++) {
            int px0 = p0 + mbase + mt * 16 + (lane >> 2);
#pragma unroll
            for (int nt = 0; nt < 8; nt++) {
                int oc = nbase + nt * 8 + (lane & 3) * 2;
                *(uint32_t*)(os + (size_t)px0 * OCN + oc) = pk_h2(accs[mt][nt][0], accs[mt][nt][1]);
                *(uint32_t*)(os + (size_t)(px0 + 8) * OCN + oc) = pk_h2(accs[mt][nt][2], accs[mt][nt][3]);
            }
        }
    }
    __syncthreads();
    if (tx < 4) {
        int g = (oc0g >> 5) + tx;
        ps[(b * NGRP + g) * 8 + blockIdx.x] = redS[tx];
        pq[(b * NGRP + g) * 8 + blockIdx.x] = redQ[tx];
    }
#undef MMA_PHASE
}

#define CONV1_SMEM (1024 + 585 * 128 + 2 * 16384)   // 108672
#define CONV2_SMEM (1024 + 204 * 128 + 2 * 16384)   // 59904

// ---------------- GN stats finalize from per-block partials ----------------
__global__ __launch_bounds__(128) void gn_fin_kernel(
    const float* __restrict__ ps, const float* __restrict__ pq, float* __restrict__ st)
{
    const int bg = threadIdx.x;    // 128 = 16*8
    float s = 0.f, q = 0.f;
#pragma unroll
    for (int i = 0; i < 8; i++) { s += ps[bg * 8 + i]; q += pq[bg * 8 + i]; }
    const float n = 32768.f;
    float mu = s / n;
    float var = q / n - mu * mu;
    st[bg * 2 + 0] = mu;
    st[bg * 2 + 1] = rsqrtf(var + EPSV);
}

// ---------------- GN1 + ReLU (fp16 in) -> padded NHWC fp16 ----------------
__global__ __launch_bounds__(256) void gn1_prep_kernel(
    const __half* __restrict__ x, const float* __restrict__ stats,
    const float* __restrict__ gamma, const float* __restrict__ beta,
    __half* __restrict__ ah)
{
    const size_t t = (size_t)blockIdx.x * 256 + threadIdx.x;
    const int c = (int)(t & 63) * 4;
    const int px = (int)((t >> 6) & 1023);
    const int b = (int)(t >> 16);
    const int bg = b * NGRP + (c >> 5);
    const float mu = stats[bg * 2], ri = stats[bg * 2 + 1];
    uint2 raw = *(const uint2*)(x + ((size_t)b * NPIX + px) * OCN + c);
    float2 x01 = uph2(raw.x), x23 = uph2(raw.y);
    float4 g4 = *(const float4*)(gamma + c);
    float4 b4 = *(const float4*)(beta + c);
    float v0 = fmaxf((x01.x - mu) * ri * g4.x + b4.x, 0.f);
    float v1 = fmaxf((x01.y - mu) * ri * g4.y + b4.y, 0.f);
    float v2 = fmaxf((x23.x - mu) * ri * g4.z + b4.z, 0.f);
    float v3 = fmaxf((x23.y - mu) * ri * g4.w + b4.w, 0.f);
    const int oh = px >> 5, ow = px & 31;
    size_t o = (((size_t)b * PW2 + oh + 1) * PW2 + ow + 1) * OCN + c;
    *(uint2*)(ah + o) = make_uint2(pk_h2(v0, v1), pk_h2(v2, v3));
}

// ---------------- final: relu(GN2(conv2) + shortcut), fp16 in -> NCHW fp32 ----------
__global__ __launch_bounds__(256) void final_kernel(
    const __half* __restrict__ x, const __half* __restrict__ sc,
    const float* __restrict__ stats,
    const float* __restrict__ gamma, const float* __restrict__ beta,
    float* __restrict__ out)
{
    __shared__ float s[32][33];
    const int pt = blockIdx.x, ct = blockIdx.y, b = blockIdx.z;
    const int px0 = pt * 32, c0 = ct * 32;
    const int tx = threadIdx.x;
    const int bg = b * NGRP + (c0 >> 5);
    const float mu = stats[bg * 2], ri = stats[bg * 2 + 1];
#pragma unroll
    for (int k = 0; k < 4; k++) {
        int idx = tx + k * 256;
        int pi = idx >> 5, ci = idx & 31;
        size_t o = ((size_t)b * NPIX + px0 + pi) * OCN + c0 + ci;
        float v = (__half2float(x[o]) - mu) * ri * gamma[c0 + ci] + beta[c0 + ci]
                + __half2float(sc[o]);
        s[pi][ci] = fmaxf(v, 0.f);
    }
    __syncthreads();
#pragma unroll
    for (int k = 0; k < 4; k++) {
        int idx = tx + k * 256;
        int cj = idx >> 5, wi = idx & 31;
        out[((size_t)b * OCN + c0 + cj) * NPIX + px0 + wi] = s[wi][cj];
    }
}

// ---------------- launch (multi-stream DAG, tensor-core weight modulation) ----------
extern "C" void kernel_launch(void* const* d_in, const int* in_sizes, int n_in,
                              void* d_out, int out_size)
{
    const float* x        = (const float*)d_in[0];
    const float* z        = (const float*)d_in[1];
    const float* base_w1  = (const float*)d_in[2];
    const float* head_w1  = (const float*)d_in[3];
    const float* head_b1  = (const float*)d_in[4];
    const float* gn_w1    = (const float*)d_in[5];
    const float* gn_b1    = (const float*)d_in[6];
    const float* base_w2  = (const float*)d_in[7];
    const float* head_w2  = (const float*)d_in[8];
    const float* head_b2  = (const float*)d_in[9];
    const float* gn_w2    = (const float*)d_in[10];
    const float* gn_b2    = (const float*)d_in[11];
    const float* base_wsc = (const float*)d_in[12];
    const float* head_wsc = (const float*)d_in[13];
    const float* head_bsc = (const float*)d_in[14];
    float* out = (float*)d_out;

    __half *xh, *ah, *w1, *w2, *ws, *c1p, *c2p, *scp;
    float *st1, *st2, *p1s, *p1q, *p2s, *p2q;
    cudaGetSymbolAddress((void**)&xh, g_xh);
    cudaGetSymbolAddress((void**)&ah, g_ah);
    cudaGetSymbolAddress((void**)&w1, g_w1);
    cudaGetSymbolAddress((void**)&w2, g_w2);
    cudaGetSymbolAddress((void**)&ws, g_ws);
    cudaGetSymbolAddress((void**)&c1p, g_c1);
    cudaGetSymbolAddress((void**)&c2p, g_c2);
    cudaGetSymbolAddress((void**)&scp, g_sc);
    cudaGetSymbolAddress((void**)&st1, g_st1);
    cudaGetSymbolAddress((void**)&st2, g_st2);
    cudaGetSymbolAddress((void**)&p1s, g_p1s);
    cudaGetSymbolAddress((void**)&p1q, g_p1q);
    cudaGetSymbolAddress((void**)&p2s, g_p2s);
    cudaGetSymbolAddress((void**)&p2q, g_p2q);

    cudaFuncSetAttribute((const void*)conv_mma_kernel<IC1, 2, PW1, 1>,
                         cudaFuncAttributeMaxDynamicSharedMemorySize, CONV1_SMEM);
    cudaFuncSetAttribute((const void*)conv_mma_kernel<OCN, 1, PW2, 0>,
                         cudaFuncAttributeMaxDynamicSharedMemorySize, CONV2_SMEM);

    static cudaStream_t sA = nullptr, sB = nullptr, sC = nullptr;
    static cudaEvent_t eFork = nullptr, eW1a = nullptr, eW1b = nullptr,
                       eW2a = nullptr, eW2b = nullptr, eWS = nullptr;
    if (sA == nullptr) {
        cudaStreamCreateWithFlags(&sA, cudaStreamNonBlocking);
        cudaStreamCreateWithFlags(&sB, cudaStreamNonBlocking);
        cudaStreamCreateWithFlags(&sC, cudaStreamNonBlocking);
        cudaEventCreateWithFlags(&eFork, cudaEventDisableTiming);
        cudaEventCreateWithFlags(&eW1a, cudaEventDisableTiming);
        cudaEventCreateWithFlags(&eW1b, cudaEventDisableTiming);
        cudaEventCreateWithFlags(&eW2a, cudaEventDisableTiming);
        cudaEventCreateWithFlags(&eW2b, cudaEventDisableTiming);
        cudaEventCreateWithFlags(&eWS, cudaEventDisableTiming);
    }

    // fork
    cudaEventRecord(eFork, 0);
    cudaStreamWaitEvent(sA, eFork, 0);
    cudaStreamWaitEvent(sB, eFork, 0);
    cudaStreamWaitEvent(sC, eFork, 0);

    const int W1BLK = (OCN * IC1 * 9) / 128;    // 2304
    const int W2BLK = (OCN * OCN * 9) / 128;    // 4608

    // sA: w1 lower half, then w2 lower half (tensor-core modulation)
    modw_mma_kernel<9, IC1><<<W1BLK / 2, 256, 0, sA>>>(base_w1, head_w1, head_b1, z, w1, 0);
    cudaEventRecord(eW1a, sA);
    modw_mma_kernel<9, OCN><<<W2BLK / 2, 256, 0, sA>>>(base_w2, head_w2, head_b2, z, w2, 0);
    cudaEventRecord(eW2a, sA);

    // sB: w1 upper half, then w2 upper half
    modw_mma_kernel<9, IC1><<<W1BLK / 2, 256, 0, sB>>>(base_w1, head_w1, head_b1, z, w1, W1BLK / 2);
    cudaEventRecord(eW1b, sB);
    modw_mma_kernel<9, OCN><<<W2BLK / 2, 256, 0, sB>>>(base_w2, head_w2, head_b2, z, w2, W2BLK / 2);
    cudaEventRecord(eW2b, sB);

    // sC: shortcut weights (exact fp32 path)
    modw1_kernel<<<(OCN * IC1) / 256, 256, 0, sC>>>(base_wsc, head_wsc, head_bsc, z, ws);
    cudaEventRecord(eWS, sC);

    // main stream: prep x (overlaps with weight mod)
    prep_x_kernel<<<dim3(8, 64, 16), 256>>>(x, xh);

    // join w1 halves + ws, then conv1 (3x3 s2) + fused shortcut + fused GN1 partials
    cudaStreamWaitEvent(0, eW1a, 0);
    cudaStreamWaitEvent(0, eW1b, 0);
    cudaStreamWaitEvent(0, eWS, 0);
    conv_mma_kernel<IC1, 2, PW1, 1><<<dim3(8, 2, 16), 256, CONV1_SMEM>>>(
        xh, w1, ws, c1p, scp, p1s, p1q);
    gn_fin_kernel<<<1, 128>>>(p1s, p1q, st1);

    // GN1 + ReLU -> padded NHWC fp16
    gn1_prep_kernel<<<(BATCH * NPIX * OCN / 4) / 256, 256>>>(c1p, st1, gn_w1, gn_b1, ah);

    // join w2 halves, then conv2 (3x3 s1) + fused GN2 partials
    cudaStreamWaitEvent(0, eW2a, 0);
    cudaStreamWaitEvent(0, eW2b, 0);
    conv_mma_kernel<OCN, 1, PW2, 0><<<dim3(8, 2, 16), 256, CONV2_SMEM>>>(
        ah, w2, (const __half*)nullptr, c2p, (__half*)nullptr, p2s, p2q);
    gn_fin_kernel<<<1, 128>>>(p2s, p2q, st2);

    // GN2 + residual + ReLU -> NCHW out
    final_kernel<<<dim3(32, 8, 16), 256>>>(c2p, scp, st2, gn_w2, gn_b2, out);
}

// round 17
// speedup vs baseline: 1.4087x; 1.4087x over previous
#include <cuda_runtime.h>
#include <cuda_fp16.h>
#include <cstdint>

// ---------------- problem dims ----------------
#define BATCH 16
#define IC1   128
#define OCN   256
#define ZDIM  64
#define HIN   64
#define WIN   64
#define HO    32
#define WO    32
#define NPIX  1024
#define NGRP  8
#define EPSV  1e-5f
#define PW1   66     // padded x: 66x66
#define PW2   34     // padded act1: 34x34

// ---------------- scratch (__device__ globals zero-init; halos stay 0) ----------------
__device__ __half g_xh [(size_t)BATCH*PW1*PW1*IC1];
__device__ __half g_ah [(size_t)BATCH*PW2*PW2*OCN];
__device__ __half g_w1 [(size_t)BATCH*9*OCN*IC1];
__device__ __half g_w2 [(size_t)BATCH*9*OCN*OCN];
__device__ __half g_ws [(size_t)BATCH*OCN*IC1];
__device__ __half g_c1 [(size_t)BATCH*NPIX*OCN];    // NHWC fp16 conv outputs
__device__ __half g_c2 [(size_t)BATCH*NPIX*OCN];
__device__ __half g_sc [(size_t)BATCH*NPIX*OCN];
__device__ float g_st1[BATCH*NGRP*2];
__device__ float g_st2[BATCH*NGRP*2];
// per-block GN partials: [b*8+g][8 px-tiles]
__device__ float g_p1s[BATCH*NGRP*8];
__device__ float g_p1q[BATCH*NGRP*8];
__device__ float g_p2s[BATCH*NGRP*8];
__device__ float g_p2q[BATCH*NGRP*8];

// ---------------- helpers ----------------
__device__ __forceinline__ uint32_t smem_u32(const void* p) {
    uint32_t a;
    asm("{ .reg .u64 t; cvta.to.shared.u64 t, %1; cvt.u32.u64 %0, t; }" : "=r"(a) : "l"(p));
    return a;
}
#define SWZ(x) ((uint32_t)(x) ^ ((((uint32_t)(x)) >> 3) & 0x70u))

#define CP16(dst, src) \
    asm volatile("cp.async.cg.shared.global [%0], [%1], 16;" :: "r"(dst), "l"(src))
#define CPCOMMIT() asm volatile("cp.async.commit_group;" ::: "memory")
#define CPWAIT0()  asm volatile("cp.async.wait_group 0;" ::: "memory")

#define LDSM4(r, addr) \
    asm volatile("ldmatrix.sync.aligned.m8n8.x4.shared.b16 {%0,%1,%2,%3}, [%4];" \
                 : "=r"((r)[0]), "=r"((r)[1]), "=r"((r)[2]), "=r"((r)[3]) : "r"(addr))

#define MMA16816(c, a, b0, b1) \
    asm volatile("mma.sync.aligned.m16n8k16.row.col.f32.f16.f16.f32 " \
                 "{%0,%1,%2,%3}, {%4,%5,%6,%7}, {%8,%9}, {%0,%1,%2,%3};" \
                 : "+f"((c)[0]), "+f"((c)[1]), "+f"((c)[2]), "+f"((c)[3]) \
                 : "r"((a)[0]), "r"((a)[1]), "r"((a)[2]), "r"((a)[3]), "r"(b0), "r"(b1))

__device__ __forceinline__ uint32_t pk_h2(float a, float b) {
    __half2 t = __floats2half2_rn(a, b);
    return *(uint32_t*)&t;
}
__device__ __forceinline__ float2 uph2(uint32_t v) {
    __half2 h = *(__half2*)&v;
    return __half22float2(h);
}

// ---------------- prep: x NCHW fp32 -> padded NHWC fp16 ----------------
__global__ __launch_bounds__(256) void prep_x_kernel(
    const float* __restrict__ x, __half* __restrict__ xh)
{
    __shared__ float s[32][33];
    const int wt = blockIdx.x & 1, ct = blockIdx.x >> 1;
    const int h = blockIdx.y, b = blockIdx.z;
    const int w0 = wt * 32, c0 = ct * 32;
    const int tx = threadIdx.x;
#pragma unroll
    for (int k = 0; k < 4; k++) {
        int idx = tx + k * 256;
        int ci = idx >> 5, wi = idx & 31;
        s[wi][ci] = x[(((size_t)b * IC1 + c0 + ci) * HIN + h) * WIN + w0 + wi];
    }
    __syncthreads();
    const int wi = tx >> 3, cg = tx & 7;
    size_t o = (((size_t)b * PW1 + h + 1) * PW1 + (w0 + wi + 1)) * IC1 + c0 + cg * 4;
    *(uint2*)(xh + o) = make_uint2(pk_h2(s[wi][cg*4+0], s[wi][cg*4+1]),
                                   pk_h2(s[wi][cg*4+2], s[wi][cg*4+3]));
}

// ---------------- weight modulation via tensor cores, coalesced epilogue ----------
// Block = one (oc, tap, ic-128-chunk): rows are 128 CONSECUTIVE ic values, so each
// batch's output is a 256B contiguous run. C-fragments go through a smem transpose
// buffer and out as uint4 stores (16 thr x 16B = 256B contiguous per batch).
// hw staged fp16 (swizzled); z as hi/lo-split fp16 B fragments (2 MMA passes).
template<int NTAP, int IC>
__global__ __launch_bounds__(256) void modw_mma_kernel(
    const float* __restrict__ base, const float* __restrict__ hw,
    const float* __restrict__ hb,   const float* __restrict__ z,
    __half* __restrict__ wout, int blk0)
{
    __shared__ __half hwS[128 * 64];
    __shared__ float cb[128];
    __shared__ __half sOut[128 * 18];          // row stride 18 halves (conflict-free)
    const int tx = threadIdx.x, lane = tx & 31, wid = tx >> 5;

    constexpr int BPO = NTAP * (IC / 128);     // blocks per oc
    const int bid = blk0 + (int)blockIdx.x;
    const int oc  = bid / BPO;
    const int rem = bid % BPO;
    const int tap = rem % NTAP;
    const int ic0 = (rem / NTAP) * 128;
    const size_t gbase = ((size_t)oc * IC + ic0) * NTAP + tap;   // row r -> gi = gbase + r*NTAP

    // stage hw rows (fp32 -> fp16, SW128 swizzled; 128B per row)
#pragma unroll
    for (int p = 0; p < 8; p++) {
        int idx = tx + p * 256;                 // float4 index
        int row = idx >> 4, k0 = (idx & 15) * 4;
        float4 v = *(const float4*)(hw + (gbase + (size_t)row * NTAP) * ZDIM + k0);
        uint32_t so = SWZ(row * 128 + k0 * 2);
        *(uint2*)((char*)hwS + so) = make_uint2(pk_h2(v.x, v.y), pk_h2(v.z, v.w));
    }
    if (tx < 128) {
        size_t gi = gbase + (size_t)tx * NTAP;
        cb[tx] = base[gi] + hb[gi];
    }

    // z B-fragments (hi/lo split), built once per thread
    uint32_t zhi[4][2][2], zlo[4][2][2];
#pragma unroll
    for (int ks = 0; ks < 4; ks++)
#pragma unroll
        for (int nt = 0; nt < 2; nt++)
#pragma unroll
            for (int rg = 0; rg < 2; rg++) {
                int n = (lane >> 2) + nt * 8;
                int k = ks * 16 + (lane & 3) * 2 + rg * 8;
                float a = z[n * ZDIM + k], bq = z[n * ZDIM + k + 1];
                __half ah = __float2half_rn(a), bh = __float2half_rn(bq);
                __half2 thi = __halves2half2(ah, bh);
                __half2 tlo = __halves2half2(__float2half_rn(a - __half2float(ah)),
                                             __float2half_rn(bq - __half2float(bh)));
                zhi[ks][nt][rg] = *(uint32_t*)&thi;
                zlo[ks][nt][rg] = *(uint32_t*)&tlo;
            }
    __syncthreads();

    float c[2][4] = {};
    const uint32_t sbase = smem_u32(hwS);
    const int arow = wid * 16 + (lane & 7) + ((lane >> 3) & 1) * 8;
    const int acol = ((lane >> 4) & 1) * 16;
#pragma unroll
    for (int ks = 0; ks < 4; ks++) {
        uint32_t a[4];
        LDSM4(a, sbase + SWZ(arow * 128 + acol + ks * 32));
#pragma unroll
        for (int nt = 0; nt < 2; nt++) {
            MMA16816(c[nt], a, zhi[ks][nt][0], zhi[ks][nt][1]);
            MMA16816(c[nt], a, zlo[ks][nt][0], zlo[ks][nt][1]);
        }
    }

    // epilogue: C fragments -> smem transpose buffer
#pragma unroll
    for (int half = 0; half < 2; half++) {
        int r = wid * 16 + (lane >> 2) + half * 8;
        float add = cb[r];
#pragma unroll
        for (int nt = 0; nt < 2; nt++) {
            int b0 = (lane & 3) * 2 + nt * 8;
            *(uint32_t*)(sOut + r * 18 + b0) =
                pk_h2(c[nt][half * 2 + 0] + add, c[nt][half * 2 + 1] + add);
        }
    }
    __syncthreads();

    // coalesced global write: thread (b, chunk) writes 8 fp16 = 16B; 16 thr/b = 256B run
    const int b = tx >> 4, chunk = tx & 15;
    __half tmp[8];
#pragma unroll
    for (int j = 0; j < 8; j++) tmp[j] = sOut[(chunk * 8 + j) * 18 + b];
    size_t o = (size_t)b * ((size_t)NTAP * OCN * IC)
             + ((size_t)tap * OCN + oc) * IC + ic0 + chunk * 8;
    *(uint4*)(wout + o) = *(uint4*)tmp;
}

// ---------------- weight modulation (1x1 shortcut): one thread per row (exact fp32) --
__global__ __launch_bounds__(256) void modw1_kernel(
    const float* __restrict__ base, const float* __restrict__ hw,
    const float* __restrict__ hb,   const float* __restrict__ z,
    __half* __restrict__ wout)
{
    __shared__ float zs[BATCH * ZDIM];
    for (int i = threadIdx.x; i < BATCH * ZDIM; i += 256) zs[i] = z[i];
    __syncthreads();

    const int i = blockIdx.x * 256 + threadIdx.x;
    float4 hwv[16];
    const float4* hwp = (const float4*)(hw + (size_t)i * ZDIM);
#pragma unroll
    for (int j = 0; j < 16; j++) hwv[j] = hwp[j];
    const float c = base[i] + hb[i];
#pragma unroll
    for (int b = 0; b < BATCH; b++) {
        const float* zb = zs + b * ZDIM;
        float acc = 0.f;
#pragma unroll
        for (int j = 0; j < 16; j++) {
            acc += hwv[j].x * zb[4*j+0];
            acc += hwv[j].y * zb[4*j+1];
            acc += hwv[j].z * zb[4*j+2];
            acc += hwv[j].w * zb[4*j+3];
        }
        wout[(size_t)b * (OCN * IC1) + i] = __float2half_rn(c + acc);
    }
}

// ---------------- conv: fp16 1-pass, A shared across taps, fused GN partials --------
template<int IC, int S, int PW, int FSC>
__global__ __launch_bounds__(256) void conv_mma_kernel(
    const __half* __restrict__ ain,
    const __half* __restrict__ win,
    const __half* __restrict__ wsin,
    __half* __restrict__ outp, __half* __restrict__ outsc,
    float* __restrict__ ps, float* __restrict__ pq)
{
    constexpr int IW_T = 31 * S + 3;
    constexpr int IH_T = 3 * S + 3;
    constexpr int APX  = IH_T * IW_T;
    constexpr int ABYT = APX * 128;
    constexpr int NT   = 9 + FSC;

    extern __shared__ char smem_raw[];
    uint32_t sb = smem_u32(smem_raw);
    sb = (sb + 1023) & ~1023u;
    const uint32_t S_A = sb, S_B = sb + ABYT;
    __shared__ float redS[4], redQ[4];

    const int tx = threadIdx.x, lane = tx & 31, wid = tx >> 5;
    const int warpM = wid & 3, warpN = wid >> 2;
    const int mbase = warpM * 32, nbase = warpN * 64;

    const int b = blockIdx.z, oc0g = blockIdx.y * 128;
    const int oh0 = blockIdx.x * 4, p0 = blockIdx.x * 128;
    const size_t abase = (size_t)b * PW * PW * IC;

    const int colsel = ((lane >> 4) & 1) * 16;
    int ohl[2], owl[2];
#pragma unroll
    for (int mt = 0; mt < 2; mt++) {
        int opx = mbase + mt * 16 + (lane & 15);
        ohl[mt] = opx >> 5; owl[mt] = opx & 31;
    }
    int rB[4];
#pragma unroll
    for (int p = 0; p < 4; p++)
        rB[p] = (nbase + p * 16 + (lane & 7) + ((lane >> 4) & 1) * 8) * 128
              + ((lane >> 3) & 1) * 16;

    float acc[2][8][4] = {};
    float accs[FSC ? 2 : 1][FSC ? 8 : 1][4] = {};

    auto stageB = [&](int icc, int tap, int buf) {
        uint32_t BH = S_B + (uint32_t)buf * 16384u;
        const __half* sh; size_t wb;
        if (FSC && tap == 9) {
            sh = wsin;
            wb = ((size_t)b * OCN + oc0g) * IC;
        } else {
            sh = win;
            wb = (((size_t)b * 9 + tap) * OCN + oc0g) * IC;
        }
#pragma unroll
        for (int pass = 0; pass < 4; pass++) {
            int i = tx + pass * 256;
            int row = i >> 3, chk = i & 7;
            size_t src = wb + (size_t)row * IC + icc * 64 + chk * 8;
            CP16(BH + SWZ(row * 128 + chk * 16), (const char*)(sh + src));
        }
    };

#define MMA_PHASE(ACC)                                                          \
    {                                                                           \
        int arow0 = (ohl[0] * S + dh) * IW_T + owl[0] * S + dw;                 \
        int arow1 = (ohl[1] * S + dh) * IW_T + owl[1] * S + dw;                 \
        _Pragma("unroll")                                                       \
        for (int ks = 0; ks < 4; ks++) {                                        \
            uint32_t ah[2][4], bfr[4][4];                                       \
            LDSM4(ah[0], S_A + SWZ(arow0 * 128 + colsel + ks * 32));            \
            LDSM4(ah[1], S_A + SWZ(arow1 * 128 + colsel + ks * 32));            \
            _Pragma("unroll")                                                   \
            for (int p = 0; p < 4; p++) LDSM4(bfr[p], SB + SWZ(rB[p] + ks * 32)); \
            _Pragma("unroll")                                                   \
            for (int mt = 0; mt < 2; mt++)                                      \
                _Pragma("unroll")                                               \
                for (int nt = 0; nt < 8; nt++)                                  \
                    MMA16816(ACC[mt][nt], ah[mt], bfr[nt >> 1][(nt & 1) * 2],   \
                             bfr[nt >> 1][(nt & 1) * 2 + 1]);                   \
        }                                                                       \
    }

#pragma unroll 1
    for (int icc = 0; icc < IC / 64; icc++) {
        __syncthreads();
        for (int i = tx; i < APX * 8; i += 256) {
            int row = i >> 3, chk = i & 7;
            int ihl = row / IW_T, iw = row - ihl * IW_T;
            size_t src = abase + ((size_t)(oh0 * S + ihl) * PW + iw) * IC
                       + icc * 64 + chk * 8;
            CP16(S_A + SWZ(row * 128 + chk * 16), (const char*)(ain + src));
        }
        stageB(icc, 0, 0);
        CPCOMMIT();

#pragma unroll 1
        for (int tap = 0; tap < NT; tap++) {
            CPWAIT0();
            __syncthreads();
            if (tap + 1 < NT) { stageB(icc, tap + 1, (tap + 1) & 1); CPCOMMIT(); }

            const int dh = (FSC && tap == 9) ? 1 : tap / 3;
            const int dw = (FSC && tap == 9) ? 1 : tap % 3;
            const uint32_t SB = S_B + (uint32_t)(tap & 1) * 16384u;
            if (FSC && tap == 9) { MMA_PHASE(accs) }
            else                 { MMA_PHASE(acc)  }
        }
    }

    // ---- epilogue: NHWC fp16 + per-group fp32 partial stats ----
    if (tx < 4) { redS[tx] = 0.f; redQ[tx] = 0.f; }
    __syncthreads();

    __half* ob = outp + (size_t)b * NPIX * OCN + oc0g;
    float s0 = 0.f, q0 = 0.f, s1 = 0.f, q1 = 0.f;
#pragma unroll
    for (int mt = 0; mt < 2; mt++) {
        int px0 = p0 + mbase + mt * 16 + (lane >> 2);
#pragma unroll
        for (int nt = 0; nt < 8; nt++) {
            int oc = nbase + nt * 8 + (lane & 3) * 2;
            *(uint32_t*)(ob + (size_t)px0 * OCN + oc) = pk_h2(acc[mt][nt][0], acc[mt][nt][1]);
            *(uint32_t*)(ob + (size_t)(px0 + 8) * OCN + oc) = pk_h2(acc[mt][nt][2], acc[mt][nt][3]);
            float ls = acc[mt][nt][0] + acc[mt][nt][1] + acc[mt][nt][2] + acc[mt][nt][3];
            float lq = acc[mt][nt][0]*acc[mt][nt][0] + acc[mt][nt][1]*acc[mt][nt][1]
                     + acc[mt][nt][2]*acc[mt][nt][2] + acc[mt][nt][3]*acc[mt][nt][3];
            if (nt < 4) { s0 += ls; q0 += lq; } else { s1 += ls; q1 += lq; }
        }
    }
#pragma unroll
    for (int off = 16; off > 0; off >>= 1) {
        s0 += __shfl_down_sync(0xffffffffu, s0, off);
        q0 += __shfl_down_sync(0xffffffffu, q0, off);
        s1 += __shfl_down_sync(0xffffffffu, s1, off);
        q1 += __shfl_down_sync(0xffffffffu, q1, off);
    }
    if (lane == 0) {
        atomicAdd(&redS[warpN * 2 + 0], s0); atomicAdd(&redQ[warpN * 2 + 0], q0);
        atomicAdd(&redS[warpN * 2 + 1], s1); atomicAdd(&redQ[warpN * 2 + 1], q1);
    }

    if (FSC) {
        __half* os = outsc + (size_t)b * NPIX * OCN + oc0g;
#pragma unroll
        for (int mt = 0; mt < 2; mt++) {
            int px0 = p0 + mbase + mt * 16 + (lane >> 2);
#pragma unroll
            for (int nt = 0; nt < 8; nt++) {
                int oc = nbase + nt * 8 + (lane & 3) * 2;
                *(uint32_t*)(os + (size_t)px0 * OCN + oc) = pk_h2(accs[mt][nt][0], accs[mt][nt][1]);
                *(uint32_t*)(os + (size_t)(px0 + 8) * OCN + oc) = pk_h2(accs[mt][nt][2], accs[mt][nt][3]);
            }
        }
    }
    __syncthreads();
    if (tx < 4) {
        int g = (oc0g >> 5) + tx;
        ps[(b * NGRP + g) * 8 + blockIdx.x] = redS[tx];
        pq[(b * NGRP + g) * 8 + blockIdx.x] = redQ[tx];
    }
#undef MMA_PHASE
}

#define CONV1_SMEM (1024 + 585 * 128 + 2 * 16384)   // 108672
#define CONV2_SMEM (1024 + 204 * 128 + 2 * 16384)   // 59904

// ---------------- GN stats finalize from per-block partials ----------------
__global__ __launch_bounds__(128) void gn_fin_kernel(
    const float* __restrict__ ps, const float* __restrict__ pq, float* __restrict__ st)
{
    const int bg = threadIdx.x;    // 128 = 16*8
    float s = 0.f, q = 0.f;
#pragma unroll
    for (int i = 0; i < 8; i++) { s += ps[bg * 8 + i]; q += pq[bg * 8 + i]; }
    const float n = 32768.f;
    float mu = s / n;
    float var = q / n - mu * mu;
    st[bg * 2 + 0] = mu;
    st[bg * 2 + 1] = rsqrtf(var + EPSV);
}

// ---------------- GN1 + ReLU (fp16 in) -> padded NHWC fp16 ----------------
__global__ __launch_bounds__(256) void gn1_prep_kernel(
    const __half* __restrict__ x, const float* __restrict__ stats,
    const float* __restrict__ gamma, const float* __restrict__ beta,
    __half* __restrict__ ah)
{
    const size_t t = (size_t)blockIdx.x * 256 + threadIdx.x;
    const int c = (int)(t & 63) * 4;
    const int px = (int)((t >> 6) & 1023);
    const int b = (int)(t >> 16);
    const int bg = b * NGRP + (c >> 5);
    const float mu = stats[bg * 2], ri = stats[bg * 2 + 1];
    uint2 raw = *(const uint2*)(x + ((size_t)b * NPIX + px) * OCN + c);
    float2 x01 = uph2(raw.x), x23 = uph2(raw.y);
    float4 g4 = *(const float4*)(gamma + c);
    float4 b4 = *(const float4*)(beta + c);
    float v0 = fmaxf((x01.x - mu) * ri * g4.x + b4.x, 0.f);
    float v1 = fmaxf((x01.y - mu) * ri * g4.y + b4.y, 0.f);
    float v2 = fmaxf((x23.x - mu) * ri * g4.z + b4.z, 0.f);
    float v3 = fmaxf((x23.y - mu) * ri * g4.w + b4.w, 0.f);
    const int oh = px >> 5, ow = px & 31;
    size_t o = (((size_t)b * PW2 + oh + 1) * PW2 + ow + 1) * OCN + c;
    *(uint2*)(ah + o) = make_uint2(pk_h2(v0, v1), pk_h2(v2, v3));
}

// ---------------- final: relu(GN2(conv2) + shortcut), fp16 in -> NCHW fp32 ----------
__global__ __launch_bounds__(256) void final_kernel(
    const __half* __restrict__ x, const __half* __restrict__ sc,
    const float* __restrict__ stats,
    const float* __restrict__ gamma, const float* __restrict__ beta,
    float* __restrict__ out)
{
    __shared__ float s[32][33];
    const int pt = blockIdx.x, ct = blockIdx.y, b = blockIdx.z;
    const int px0 = pt * 32, c0 = ct * 32;
    const int tx = threadIdx.x;
    const int bg = b * NGRP + (c0 >> 5);
    const float mu = stats[bg * 2], ri = stats[bg * 2 + 1];
#pragma unroll
    for (int k = 0; k < 4; k++) {
        int idx = tx + k * 256;
        int pi = idx >> 5, ci = idx & 31;
        size_t o = ((size_t)b * NPIX + px0 + pi) * OCN + c0 + ci;
        float v = (__half2float(x[o]) - mu) * ri * gamma[c0 + ci] + beta[c0 + ci]
                + __half2float(sc[o]);
        s[pi][ci] = fmaxf(v, 0.f);
    }
    __syncthreads();
#pragma unroll
    for (int k = 0; k < 4; k++) {
        int idx = tx + k * 256;
        int cj = idx >> 5, wi = idx & 31;
        out[((size_t)b * OCN + c0 + cj) * NPIX + px0 + wi] = s[wi][cj];
    }
}

// ---------------- launch (multi-stream DAG, tensor-core weight modulation) ----------
extern "C" void kernel_launch(void* const* d_in, const int* in_sizes, int n_in,
                              void* d_out, int out_size)
{
    const float* x        = (const float*)d_in[0];
    const float* z        = (const float*)d_in[1];
    const float* base_w1  = (const float*)d_in[2];
    const float* head_w1  = (const float*)d_in[3];
    const float* head_b1  = (const float*)d_in[4];
    const float* gn_w1    = (const float*)d_in[5];
    const float* gn_b1    = (const float*)d_in[6];
    const float* base_w2  = (const float*)d_in[7];
    const float* head_w2  = (const float*)d_in[8];
    const float* head_b2  = (const float*)d_in[9];
    const float* gn_w2    = (const float*)d_in[10];
    const float* gn_b2    = (const float*)d_in[11];
    const float* base_wsc = (const float*)d_in[12];
    const float* head_wsc = (const float*)d_in[13];
    const float* head_bsc = (const float*)d_in[14];
    float* out = (float*)d_out;

    __half *xh, *ah, *w1, *w2, *ws, *c1p, *c2p, *scp;
    float *st1, *st2, *p1s, *p1q, *p2s, *p2q;
    cudaGetSymbolAddress((void**)&xh, g_xh);
    cudaGetSymbolAddress((void**)&ah, g_ah);
    cudaGetSymbolAddress((void**)&w1, g_w1);
    cudaGetSymbolAddress((void**)&w2, g_w2);
    cudaGetSymbolAddress((void**)&ws, g_ws);
    cudaGetSymbolAddress((void**)&c1p, g_c1);
    cudaGetSymbolAddress((void**)&c2p, g_c2);
    cudaGetSymbolAddress((void**)&scp, g_sc);
    cudaGetSymbolAddress((void**)&st1, g_st1);
    cudaGetSymbolAddress((void**)&st2, g_st2);
    cudaGetSymbolAddress((void**)&p1s, g_p1s);
    cudaGetSymbolAddress((void**)&p1q, g_p1q);
    cudaGetSymbolAddress((void**)&p2s, g_p2s);
    cudaGetSymbolAddress((void**)&p2q, g_p2q);

    cudaFuncSetAttribute((const void*)conv_mma_kernel<IC1, 2, PW1, 1>,
                         cudaFuncAttributeMaxDynamicSharedMemorySize, CONV1_SMEM);
    cudaFuncSetAttribute((const void*)conv_mma_kernel<OCN, 1, PW2, 0>,
                         cudaFuncAttributeMaxDynamicSharedMemorySize, CONV2_SMEM);

    static cudaStream_t sA = nullptr, sB = nullptr, sC = nullptr;
    static cudaEvent_t eFork = nullptr, eW1a = nullptr, eW1b = nullptr,
                       eW2a = nullptr, eW2b = nullptr, eWS = nullptr;
    if (sA == nullptr) {
        cudaStreamCreateWithFlags(&sA, cudaStreamNonBlocking);
        cudaStreamCreateWithFlags(&sB, cudaStreamNonBlocking);
        cudaStreamCreateWithFlags(&sC, cudaStreamNonBlocking);
        cudaEventCreateWithFlags(&eFork, cudaEventDisableTiming);
        cudaEventCreateWithFlags(&eW1a, cudaEventDisableTiming);
        cudaEventCreateWithFlags(&eW1b, cudaEventDisableTiming);
        cudaEventCreateWithFlags(&eW2a, cudaEventDisableTiming);
        cudaEventCreateWithFlags(&eW2b, cudaEventDisableTiming);
        cudaEventCreateWithFlags(&eWS, cudaEventDisableTiming);
    }

    // fork
    cudaEventRecord(eFork, 0);
    cudaStreamWaitEvent(sA, eFork, 0);
    cudaStreamWaitEvent(sB, eFork, 0);
    cudaStreamWaitEvent(sC, eFork, 0);

    const int W1BLK = (OCN * IC1 * 9) / 128;    // 2304
    const int W2BLK = (OCN * OCN * 9) / 128;    // 4608

    // sA: w1 lower half, then w2 lower half (tensor-core modulation)
    modw_mma_kernel<9, IC1><<<W1BLK / 2, 256, 0, sA>>>(base_w1, head_w1, head_b1, z, w1, 0);
    cudaEventRecord(eW1a, sA);
    modw_mma_kernel<9, OCN><<<W2BLK / 2, 256, 0, sA>>>(base_w2, head_w2, head_b2, z, w2, 0);
    cudaEventRecord(eW2a, sA);

    // sB: w1 upper half, then w2 upper half
    modw_mma_kernel<9, IC1><<<W1BLK / 2, 256, 0, sB>>>(base_w1, head_w1, head_b1, z, w1, W1BLK / 2);
    cudaEventRecord(eW1b, sB);
    modw_mma_kernel<9, OCN><<<W2BLK / 2, 256, 0, sB>>>(base_w2, head_w2, head_b2, z, w2, W2BLK / 2);
    cudaEventRecord(eW2b, sB);

    // sC: shortcut weights (exact fp32 path)
    modw1_kernel<<<(OCN * IC1) / 256, 256, 0, sC>>>(base_wsc, head_wsc, head_bsc, z, ws);
    cudaEventRecord(eWS, sC);

    // main stream: prep x (overlaps with weight mod)
    prep_x_kernel<<<dim3(8, 64, 16), 256>>>(x, xh);

    // join w1 halves + ws, then conv1 (3x3 s2) + fused shortcut + fused GN1 partials
    cudaStreamWaitEvent(0, eW1a, 0);
    cudaStreamWaitEvent(0, eW1b, 0);
    cudaStreamWaitEvent(0, eWS, 0);
    conv_mma_kernel<IC1, 2, PW1, 1><<<dim3(8, 2, 16), 256, CONV1_SMEM>>>(
        xh, w1, ws, c1p, scp, p1s, p1q);
    gn_fin_kernel<<<1, 128>>>(p1s, p1q, st1);

    // GN1 + ReLU -> padded NHWC fp16
    gn1_prep_kernel<<<(BATCH * NPIX * OCN / 4) / 256, 256>>>(c1p, st1, gn_w1, gn_b1, ah);

    // join w2 halves, then conv2 (3x3 s1) + fused GN2 partials
    cudaStreamWaitEvent(0, eW2a, 0);
    cudaStreamWaitEvent(0, eW2b, 0);
    conv_mma_kernel<OCN, 1, PW2, 0><<<dim3(8, 2, 16), 256, CONV2_SMEM>>>(
        ah, w2, (const __half*)nullptr, c2p, (__half*)nullptr, p2s, p2q);
    gn_fin_kernel<<<1, 128>>>(p2s, p2q, st2);

    // GN2 + residual + ReLU -> NCHW out
    final_kernel<<<dim3(32, 8, 16), 256>>>(c2p, scp, st2, gn_w2, gn_b2, out);
}